// round 2
// baseline (speedup 1.0000x reference)
#include <cuda_runtime.h>

#define NODES_MAX 100000
#define H 128

// Scratch (static device globals — no allocations allowed)
__device__ float g_AI[(size_t)NODES_MAX * H];
__device__ float g_Wt[H * H];
__device__ int g_idx64;   // 1 if rows/cols are int64, 0 if int32

// ---------------------------------------------------------------------------
// Detect index dtype: int64 data has zero high-words at odd int32 positions.
// ---------------------------------------------------------------------------
__global__ void detect_idx_dtype(const int* __restrict__ rows, int n_edges) {
    int or_odd = 0;
    int lim = min(n_edges, 128);   // safe: reads < n_edges ints either way
    for (int i = 1; i < lim; i += 2) or_odd |= rows[i];
    g_idx64 = (or_odd == 0) ? 1 : 0;
}

// ---------------------------------------------------------------------------
// Transpose W[o][h] -> Wt[h][o] (tiny, 64 KB)
// ---------------------------------------------------------------------------
__global__ void transpose_W(const float* __restrict__ W) {
    int i = blockIdx.x * blockDim.x + threadIdx.x;
    if (i < H * H) {
        int o = i / H, h = i % H;
        g_Wt[h * H + o] = W[i];
    }
}

// ---------------------------------------------------------------------------
// Zero AI scratch (float4 grid-stride)
// ---------------------------------------------------------------------------
__global__ void zero_AI(int n_nodes) {
    int total = n_nodes * (H / 4);
    float4* p = reinterpret_cast<float4*>(g_AI);
    for (int i = blockIdx.x * blockDim.x + threadIdx.x; i < total;
         i += gridDim.x * blockDim.x) {
        p[i] = make_float4(0.f, 0.f, 0.f, 0.f);
    }
}

// ---------------------------------------------------------------------------
// sigmoid(x[s] @ W^T + b) for s in {0,1} -> out slice s  (S and I staged in out)
// Block: 64 nodes x 128 outputs, 256 threads, each thread 8x4 micro-tile.
// ---------------------------------------------------------------------------
__global__ __launch_bounds__(256) void gemm_sigmoid(
    const float* __restrict__ x, const float* __restrict__ b,
    float* __restrict__ out, int n_nodes)
{
    __shared__ float Xs[64 * H];

    const int s = blockIdx.y;
    const int node0 = blockIdx.x * 64;
    const int tid = threadIdx.x;
    const float* xs = x + ((size_t)s * n_nodes + node0) * H;

    const int maxm = min(64, n_nodes - node0);
    float4* Xs4w = reinterpret_cast<float4*>(Xs);
    const float4* xsrc = reinterpret_cast<const float4*>(xs);
    for (int i = tid; i < 64 * (H / 4); i += 256) {
        int m = i >> 5;  // i / 32
        float4 v = make_float4(0.f, 0.f, 0.f, 0.f);
        if (m < maxm) v = xsrc[(size_t)m * (H / 4) + (i & 31)];
        Xs4w[i] = v;
    }
    __syncthreads();

    const int tx = tid & 31;   // output group: o = tx*4 .. tx*4+3
    const int ty = tid >> 5;   // node group:   m = ty*8 .. ty*8+7

    const float4* Wt4 = reinterpret_cast<const float4*>(g_Wt);
    const float4* Xs4 = reinterpret_cast<const float4*>(Xs);

    float4 bb = reinterpret_cast<const float4*>(b)[tx];
    float acc[8][4];
#pragma unroll
    for (int mm = 0; mm < 8; mm++) {
        acc[mm][0] = bb.x; acc[mm][1] = bb.y;
        acc[mm][2] = bb.z; acc[mm][3] = bb.w;
    }

    for (int kk = 0; kk < H / 4; kk++) {
        float4 w0 = __ldg(&Wt4[(4 * kk + 0) * (H / 4) + tx]);
        float4 w1 = __ldg(&Wt4[(4 * kk + 1) * (H / 4) + tx]);
        float4 w2 = __ldg(&Wt4[(4 * kk + 2) * (H / 4) + tx]);
        float4 w3 = __ldg(&Wt4[(4 * kk + 3) * (H / 4) + tx]);
#pragma unroll
        for (int mm = 0; mm < 8; mm++) {
            float4 xv = Xs4[(ty * 8 + mm) * (H / 4) + kk];
            acc[mm][0] += xv.x * w0.x + xv.y * w1.x + xv.z * w2.x + xv.w * w3.x;
            acc[mm][1] += xv.x * w0.y + xv.y * w1.y + xv.z * w2.y + xv.w * w3.y;
            acc[mm][2] += xv.x * w0.z + xv.y * w1.z + xv.z * w2.z + xv.w * w3.z;
            acc[mm][3] += xv.x * w0.w + xv.y * w1.w + xv.z * w2.w + xv.w * w3.w;
        }
    }

    float* outp = out + ((size_t)s * n_nodes + node0) * H;
#pragma unroll
    for (int mm = 0; mm < 8; mm++) {
        int m = ty * 8 + mm;
        if (m < maxm) {
            float4 r;
            r.x = 1.f / (1.f + __expf(-acc[mm][0]));
            r.y = 1.f / (1.f + __expf(-acc[mm][1]));
            r.z = 1.f / (1.f + __expf(-acc[mm][2]));
            r.w = 1.f / (1.f + __expf(-acc[mm][3]));
            reinterpret_cast<float4*>(outp)[(size_t)m * (H / 4) + tx] = r;
        }
    }
}

// ---------------------------------------------------------------------------
// Edge scatter: AI[rows[e]] += I[cols[e]]  (128 floats / edge, 1 warp / edge)
// Gather LDG.128 + red.global.add.v4.f32 — both L2-resident (I, AI ~51 MB each)
// Index width resolved at runtime via g_idx64 (uniform branch).
// ---------------------------------------------------------------------------
__global__ __launch_bounds__(256) void edge_kernel(
    const int* __restrict__ rows,
    const int* __restrict__ cols,
    const float* __restrict__ I,   // out slice 1
    int n_edges)
{
    const int lane = threadIdx.x & 31;
    const int warp = (blockIdx.x * blockDim.x + threadIdx.x) >> 5;
    const int n_warps = (gridDim.x * blockDim.x) >> 5;
    const int is64 = g_idx64;

    for (int e = warp; e < n_edges; e += n_warps) {
        int ei = is64 ? (2 * e) : e;
        int r = rows[ei];
        int c = cols[ei];
        float4 v = *reinterpret_cast<const float4*>(I + (size_t)c * H + lane * 4);
        float* dst = g_AI + (size_t)r * H + lane * 4;
        asm volatile("red.global.add.v4.f32 [%0], {%1, %2, %3, %4};"
                     :: "l"(dst), "f"(v.x), "f"(v.y), "f"(v.z), "f"(v.w)
                     : "memory");
    }
}

// ---------------------------------------------------------------------------
// Epilogue: dS = -beta*AI*S ; dI = -dS - gamma*I ; dR = gamma*I ; slice3 = 0
// Reads S,I from out slices 0,1 (same-thread read-then-write: safe)
// ---------------------------------------------------------------------------
__global__ __launch_bounds__(256) void finalize(
    const float* __restrict__ x, float* __restrict__ out, int n_nodes)
{
    int idx = blockIdx.x * blockDim.x + threadIdx.x;
    int total = n_nodes * (H / 4);
    if (idx >= total) return;

    int n = idx >> 5;
    float beta  = x[((size_t)3 * n_nodes + n) * H + 0];
    float gamma = x[((size_t)3 * n_nodes + n) * H + 1];

    float4* o4 = reinterpret_cast<float4*>(out);
    size_t sl = (size_t)n_nodes * (H / 4);

    float4 S  = o4[idx];
    float4 I  = o4[sl + idx];
    float4 ai = reinterpret_cast<const float4*>(g_AI)[idx];

    float4 dS, dI, dR;
    dS.x = -beta * ai.x * S.x;  dS.y = -beta * ai.y * S.y;
    dS.z = -beta * ai.z * S.z;  dS.w = -beta * ai.w * S.w;
    dI.x = -dS.x - gamma * I.x; dI.y = -dS.y - gamma * I.y;
    dI.z = -dS.z - gamma * I.z; dI.w = -dS.w - gamma * I.w;
    dR.x = gamma * I.x;  dR.y = gamma * I.y;
    dR.z = gamma * I.z;  dR.w = gamma * I.w;

    o4[idx] = dS;
    o4[sl + idx] = dI;
    o4[2 * sl + idx] = dR;
    o4[3 * sl + idx] = make_float4(0.f, 0.f, 0.f, 0.f);
}

// ---------------------------------------------------------------------------
extern "C" void kernel_launch(void* const* d_in, const int* in_sizes, int n_in,
                              void* d_out, int out_size)
{
    const float* x = (const float*)d_in[0];
    const float* W = (const float*)d_in[1];
    const float* b = (const float*)d_in[2];
    const int* rows = (const int*)d_in[3];
    const int* cols = (const int*)d_in[4];
    float* out = (float*)d_out;

    int n_nodes = in_sizes[0] / (4 * H);
    int n_edges = in_sizes[3];

    detect_idx_dtype<<<1, 1>>>(rows, n_edges);
    transpose_W<<<(H * H + 255) / 256, 256>>>(W);
    zero_AI<<<1024, 256>>>(n_nodes);

    dim3 g((n_nodes + 63) / 64, 2);
    gemm_sigmoid<<<g, 256>>>(x, b, out, n_nodes);

    edge_kernel<<<4096, 256>>>(rows, cols, out + (size_t)n_nodes * H, n_edges);

    finalize<<<(n_nodes * (H / 4) + 255) / 256, 256>>>(x, out, n_nodes);
}

// round 4
// speedup vs baseline: 1.2580x; 1.2580x over previous
#include <cuda_runtime.h>

#define NODES_MAX 100000
#define EDGES_MAX 1600000
#define H 128
#define NB_SCAN 128

// Scratch (static device globals — no allocations allowed)
__device__ float g_AI[(size_t)NODES_MAX * H];
__device__ float g_Wt[H * H];
__device__ int g_idx64;                    // 1 if rows/cols int64, 0 if int32
__device__ int g_cnt[NODES_MAX];
__device__ int g_rowptr[NODES_MAX + 1];
__device__ int g_off[NODES_MAX];
__device__ int g_partial[NB_SCAN];
__device__ int g_edges[EDGES_MAX];

// ---------------------------------------------------------------------------
// Detect index dtype: int64 data has zero high-words at odd int32 positions.
// ---------------------------------------------------------------------------
__global__ void detect_idx_dtype(const int* __restrict__ rows, int n_edges) {
    int or_odd = 0;
    int lim = min(n_edges, 128);
    for (int i = 1; i < lim; i += 2) or_odd |= rows[i];
    g_idx64 = (or_odd == 0) ? 1 : 0;
}

// ---------------------------------------------------------------------------
// Transpose W[o][h] -> Wt[h][o]
// ---------------------------------------------------------------------------
__global__ void transpose_W(const float* __restrict__ W) {
    int i = blockIdx.x * blockDim.x + threadIdx.x;
    if (i < H * H) {
        int o = i / H, h = i % H;
        g_Wt[h * H + o] = W[i];
    }
}

// ---------------------------------------------------------------------------
// CSR binning: zero counts -> count -> scan (3 kernels) -> fill
// ---------------------------------------------------------------------------
__global__ void zero_cnt(int n_nodes) {
    int i = blockIdx.x * blockDim.x + threadIdx.x;
    if (i < n_nodes) g_cnt[i] = 0;
}

__global__ void count_rows(const int* __restrict__ rows, int n_edges) {
    const int is64 = g_idx64;
    for (int e = blockIdx.x * blockDim.x + threadIdx.x; e < n_edges;
         e += gridDim.x * blockDim.x) {
        int r = rows[is64 ? 2 * e : e];
        atomicAdd(&g_cnt[r], 1);
    }
}

__global__ void scanA(int n_nodes) {
    __shared__ int sm[256];
    int chunk = (n_nodes + NB_SCAN - 1) / NB_SCAN;
    int b = blockIdx.x;
    int lo = b * chunk, hi = min(lo + chunk, n_nodes);
    int s = 0;
    for (int i = lo + threadIdx.x; i < hi; i += 256) s += g_cnt[i];
    sm[threadIdx.x] = s;
    __syncthreads();
    for (int off = 128; off > 0; off >>= 1) {
        if (threadIdx.x < off) sm[threadIdx.x] += sm[threadIdx.x + off];
        __syncthreads();
    }
    if (threadIdx.x == 0) g_partial[b] = sm[0];
}

__global__ void scanB() {
    __shared__ int sm[NB_SCAN];
    int tid = threadIdx.x;
    int own = g_partial[tid];
    sm[tid] = own;
    __syncthreads();
    for (int off = 1; off < NB_SCAN; off <<= 1) {
        int v = (tid >= off) ? sm[tid - off] : 0;
        __syncthreads();
        sm[tid] += v;
        __syncthreads();
    }
    g_partial[tid] = sm[tid] - own;   // exclusive base
}

__global__ void scanC(int n_nodes) {
    int b = blockIdx.x;
    int lane = threadIdx.x;  // blockDim = 32
    int chunk = (n_nodes + NB_SCAN - 1) / NB_SCAN;
    int lo = b * chunk, hi = min(lo + chunk, n_nodes);
    if (lo >= n_nodes) return;
    int carry = g_partial[b];
    for (int i0 = lo; i0 < hi; i0 += 32) {
        int i = i0 + lane;
        int v = (i < hi) ? g_cnt[i] : 0;
        int incl = v;
        for (int off = 1; off < 32; off <<= 1) {
            int t = __shfl_up_sync(0xffffffffu, incl, off);
            if (lane >= off) incl += t;
        }
        int excl = incl - v;
        if (i < hi) {
            g_rowptr[i] = carry + excl;
            g_off[i] = carry + excl;
        }
        carry += __shfl_sync(0xffffffffu, incl, 31);
    }
    if (lane == 0 && hi == n_nodes) g_rowptr[n_nodes] = carry;
}

__global__ void fill_edges(const int* __restrict__ rows,
                           const int* __restrict__ cols, int n_edges) {
    const int is64 = g_idx64;
    for (int e = blockIdx.x * blockDim.x + threadIdx.x; e < n_edges;
         e += gridDim.x * blockDim.x) {
        int ei = is64 ? 2 * e : e;
        int r = rows[ei];
        int c = cols[ei];
        int pos = atomicAdd(&g_off[r], 1);
        g_edges[pos] = c;
    }
}

// ---------------------------------------------------------------------------
// sigmoid(x[s] @ W^T + b) for s in {0,1} -> out slice s
// 64 nodes x 128 outputs per CTA, 256 threads.
// Packed fp32 (fma.rn.f32x2): node-pairs packed via transposed smem tile.
// Thread micro-tile: 8 nodes (4 pairs) x 4 outputs.
// XPAD must be EVEN so 64-bit LDS of node-pairs stays 8-byte aligned.
// ---------------------------------------------------------------------------
#define XPAD 66
__global__ __launch_bounds__(256, 3) void gemm_sigmoid(
    const float* __restrict__ x, const float* __restrict__ b,
    float* __restrict__ out, int n_nodes)
{
    __shared__ float XsT[H * XPAD];  // [k][node], padded (even pad!)

    const int s = blockIdx.y;
    const int node0 = blockIdx.x * 64;
    const int tid = threadIdx.x;
    const float* xs = x + ((size_t)s * n_nodes + node0) * H;
    const int maxm = min(64, n_nodes - node0);

    // Load x tile transposed: i -> (m = i>>5, quad q = i&31) ; coalesced gmem.
    const float4* xsrc = reinterpret_cast<const float4*>(xs);
    for (int i = tid; i < 64 * (H / 4); i += 256) {
        int m = i >> 5, q = i & 31;
        float4 v = make_float4(0.f, 0.f, 0.f, 0.f);
        if (m < maxm) v = xsrc[(size_t)m * (H / 4) + q];
        XsT[(4 * q + 0) * XPAD + m] = v.x;
        XsT[(4 * q + 1) * XPAD + m] = v.y;
        XsT[(4 * q + 2) * XPAD + m] = v.z;
        XsT[(4 * q + 3) * XPAD + m] = v.w;
    }
    __syncthreads();

    const int tx = tid & 31;   // outputs 4tx..4tx+3
    const int ty = tid >> 5;   // nodes ty*8 .. ty*8+7 (4 pairs)

    const float4* Wt4 = reinterpret_cast<const float4*>(g_Wt);
    float4 bb = reinterpret_cast<const float4*>(b)[tx];

    unsigned long long acc[4][4];  // [pair][output]
    {
        unsigned long long b0, b1, b2, b3;
        asm("mov.b64 %0, {%1, %1};" : "=l"(b0) : "f"(bb.x));
        asm("mov.b64 %0, {%1, %1};" : "=l"(b1) : "f"(bb.y));
        asm("mov.b64 %0, {%1, %1};" : "=l"(b2) : "f"(bb.z));
        asm("mov.b64 %0, {%1, %1};" : "=l"(b3) : "f"(bb.w));
#pragma unroll
        for (int p = 0; p < 4; p++) {
            acc[p][0] = b0; acc[p][1] = b1; acc[p][2] = b2; acc[p][3] = b3;
        }
    }

    const int mbase = ty * 8;
#pragma unroll 2
    for (int k = 0; k < H; k++) {
        float4 w = __ldg(&Wt4[k * (H / 4) + tx]);
        unsigned long long wd[4];
        asm("mov.b64 %0, {%1, %1};" : "=l"(wd[0]) : "f"(w.x));
        asm("mov.b64 %0, {%1, %1};" : "=l"(wd[1]) : "f"(w.y));
        asm("mov.b64 %0, {%1, %1};" : "=l"(wd[2]) : "f"(w.z));
        asm("mov.b64 %0, {%1, %1};" : "=l"(wd[3]) : "f"(w.w));

        const float* xrow = &XsT[k * XPAD + mbase];   // even index -> 8B aligned
        unsigned long long xp[4];
#pragma unroll
        for (int p = 0; p < 4; p++)
            xp[p] = *reinterpret_cast<const unsigned long long*>(xrow + 2 * p);

#pragma unroll
        for (int p = 0; p < 4; p++) {
#pragma unroll
            for (int j = 0; j < 4; j++) {
                asm("fma.rn.f32x2 %0, %1, %2, %0;"
                    : "+l"(acc[p][j]) : "l"(xp[p]), "l"(wd[j]));
            }
        }
    }

    float* outp = out + ((size_t)s * n_nodes + node0) * H;
#pragma unroll
    for (int p = 0; p < 4; p++) {
        float lo[4], hi[4];
#pragma unroll
        for (int j = 0; j < 4; j++)
            asm("mov.b64 {%0, %1}, %2;" : "=f"(lo[j]), "=f"(hi[j]) : "l"(acc[p][j]));
        int m0 = mbase + 2 * p, m1 = m0 + 1;
        if (m0 < maxm) {
            float4 r;
            r.x = 1.f / (1.f + __expf(-lo[0]));
            r.y = 1.f / (1.f + __expf(-lo[1]));
            r.z = 1.f / (1.f + __expf(-lo[2]));
            r.w = 1.f / (1.f + __expf(-lo[3]));
            reinterpret_cast<float4*>(outp)[(size_t)m0 * (H / 4) + tx] = r;
        }
        if (m1 < maxm) {
            float4 r;
            r.x = 1.f / (1.f + __expf(-hi[0]));
            r.y = 1.f / (1.f + __expf(-hi[1]));
            r.z = 1.f / (1.f + __expf(-hi[2]));
            r.w = 1.f / (1.f + __expf(-hi[3]));
            reinterpret_cast<float4*>(outp)[(size_t)m1 * (H / 4) + tx] = r;
        }
    }
}

// ---------------------------------------------------------------------------
// CSR aggregation: one warp per row; accumulate gathered I rows in registers,
// store AI once (no atomics, no zero pass).
// ---------------------------------------------------------------------------
__global__ __launch_bounds__(256) void aggregate(
    const float* __restrict__ I, int n_nodes)
{
    const int lane = threadIdx.x & 31;
    const int r = (blockIdx.x * blockDim.x + threadIdx.x) >> 5;
    if (r >= n_nodes) return;

    int e = g_rowptr[r];
    const int end = g_rowptr[r + 1];
    const float4* I4 = reinterpret_cast<const float4*>(I);

    float4 acc = make_float4(0.f, 0.f, 0.f, 0.f);
    for (; e + 1 < end; e += 2) {
        int c0 = g_edges[e], c1 = g_edges[e + 1];
        float4 v0 = I4[(size_t)c0 * (H / 4) + lane];
        float4 v1 = I4[(size_t)c1 * (H / 4) + lane];
        acc.x += v0.x + v1.x; acc.y += v0.y + v1.y;
        acc.z += v0.z + v1.z; acc.w += v0.w + v1.w;
    }
    if (e < end) {
        int c = g_edges[e];
        float4 v = I4[(size_t)c * (H / 4) + lane];
        acc.x += v.x; acc.y += v.y; acc.z += v.z; acc.w += v.w;
    }
    reinterpret_cast<float4*>(g_AI)[(size_t)r * (H / 4) + lane] = acc;
}

// ---------------------------------------------------------------------------
// Epilogue: dS = -beta*AI*S ; dI = -dS - gamma*I ; dR = gamma*I ; slice3 = 0
// ---------------------------------------------------------------------------
__global__ __launch_bounds__(256) void finalize(
    const float* __restrict__ x, float* __restrict__ out, int n_nodes)
{
    int idx = blockIdx.x * blockDim.x + threadIdx.x;
    int total = n_nodes * (H / 4);
    if (idx >= total) return;

    int n = idx >> 5;
    float beta  = x[((size_t)3 * n_nodes + n) * H + 0];
    float gamma = x[((size_t)3 * n_nodes + n) * H + 1];

    float4* o4 = reinterpret_cast<float4*>(out);
    size_t sl = (size_t)n_nodes * (H / 4);

    float4 S  = o4[idx];
    float4 I  = o4[sl + idx];
    float4 ai = reinterpret_cast<const float4*>(g_AI)[idx];

    float4 dS, dI, dR;
    dS.x = -beta * ai.x * S.x;  dS.y = -beta * ai.y * S.y;
    dS.z = -beta * ai.z * S.z;  dS.w = -beta * ai.w * S.w;
    dI.x = -dS.x - gamma * I.x; dI.y = -dS.y - gamma * I.y;
    dI.z = -dS.z - gamma * I.z; dI.w = -dS.w - gamma * I.w;
    dR.x = gamma * I.x;  dR.y = gamma * I.y;
    dR.z = gamma * I.z;  dR.w = gamma * I.w;

    o4[idx] = dS;
    o4[sl + idx] = dI;
    o4[2 * sl + idx] = dR;
    o4[3 * sl + idx] = make_float4(0.f, 0.f, 0.f, 0.f);
}

// ---------------------------------------------------------------------------
extern "C" void kernel_launch(void* const* d_in, const int* in_sizes, int n_in,
                              void* d_out, int out_size)
{
    const float* x = (const float*)d_in[0];
    const float* W = (const float*)d_in[1];
    const float* b = (const float*)d_in[2];
    const int* rows = (const int*)d_in[3];
    const int* cols = (const int*)d_in[4];
    float* out = (float*)d_out;

    int n_nodes = in_sizes[0] / (4 * H);
    int n_edges = in_sizes[3];

    detect_idx_dtype<<<1, 1>>>(rows, n_edges);
    transpose_W<<<(H * H + 255) / 256, 256>>>(W);

    // CSR binning
    zero_cnt<<<(n_nodes + 255) / 256, 256>>>(n_nodes);
    count_rows<<<2048, 256>>>(rows, n_edges);
    scanA<<<NB_SCAN, 256>>>(n_nodes);
    scanB<<<1, NB_SCAN>>>();
    scanC<<<NB_SCAN, 32>>>(n_nodes);
    fill_edges<<<2048, 256>>>(rows, cols, n_edges);

    // GEMM + sigmoid for S, I
    dim3 g((n_nodes + 63) / 64, 2);
    gemm_sigmoid<<<g, 256>>>(x, b, out, n_nodes);

    // AI = segment-sum of gathered I rows
    aggregate<<<(n_nodes * 32 + 255) / 256, 256>>>(out + (size_t)n_nodes * H,
                                                   n_nodes);

    finalize<<<(n_nodes * (H / 4) + 255) / 256, 256>>>(x, out, n_nodes);
}

// round 5
// speedup vs baseline: 1.3586x; 1.0800x over previous
#include <cuda_runtime.h>

#define NODES_MAX 100000
#define EDGES_MAX 1600000
#define H 128
#define NB_SCAN 128

// Scratch (static device globals — no allocations allowed)
__device__ float g_I[(size_t)NODES_MAX * H];   // sigmoid GEMM output for I
__device__ float g_Wt[H * H];
__device__ int g_idx64;                    // 1 if rows/cols int64, 0 if int32
__device__ int g_cnt[NODES_MAX];
__device__ int g_rowptr[NODES_MAX + 1];
__device__ int g_off[NODES_MAX];
__device__ int g_partial[NB_SCAN];
__device__ int g_edges[EDGES_MAX];

// ---------------------------------------------------------------------------
// Detect index dtype: int64 data has zero high-words at odd int32 positions.
// ---------------------------------------------------------------------------
__global__ void detect_idx_dtype(const int* __restrict__ rows, int n_edges) {
    int or_odd = 0;
    int lim = min(n_edges, 128);
    for (int i = 1; i < lim; i += 2) or_odd |= rows[i];
    g_idx64 = (or_odd == 0) ? 1 : 0;
}

// ---------------------------------------------------------------------------
// Transpose W[o][h] -> Wt[h][o]
// ---------------------------------------------------------------------------
__global__ void transpose_W(const float* __restrict__ W) {
    int i = blockIdx.x * blockDim.x + threadIdx.x;
    if (i < H * H) {
        int o = i / H, h = i % H;
        g_Wt[h * H + o] = W[i];
    }
}

// ---------------------------------------------------------------------------
// CSR binning: zero counts -> count -> scan (3 kernels) -> fill
// ---------------------------------------------------------------------------
__global__ void zero_cnt(int n_nodes) {
    int i = blockIdx.x * blockDim.x + threadIdx.x;
    if (i < n_nodes) g_cnt[i] = 0;
}

__global__ void count_rows(const int* __restrict__ rows, int n_edges) {
    const int is64 = g_idx64;
    for (int e = blockIdx.x * blockDim.x + threadIdx.x; e < n_edges;
         e += gridDim.x * blockDim.x) {
        int r = rows[is64 ? 2 * e : e];
        atomicAdd(&g_cnt[r], 1);
    }
}

__global__ void scanA(int n_nodes) {
    __shared__ int sm[256];
    int chunk = (n_nodes + NB_SCAN - 1) / NB_SCAN;
    int b = blockIdx.x;
    int lo = b * chunk, hi = min(lo + chunk, n_nodes);
    int s = 0;
    for (int i = lo + threadIdx.x; i < hi; i += 256) s += g_cnt[i];
    sm[threadIdx.x] = s;
    __syncthreads();
    for (int off = 128; off > 0; off >>= 1) {
        if (threadIdx.x < off) sm[threadIdx.x] += sm[threadIdx.x + off];
        __syncthreads();
    }
    if (threadIdx.x == 0) g_partial[b] = sm[0];
}

__global__ void scanB() {
    __shared__ int sm[NB_SCAN];
    int tid = threadIdx.x;
    int own = g_partial[tid];
    sm[tid] = own;
    __syncthreads();
    for (int off = 1; off < NB_SCAN; off <<= 1) {
        int v = (tid >= off) ? sm[tid - off] : 0;
        __syncthreads();
        sm[tid] += v;
        __syncthreads();
    }
    g_partial[tid] = sm[tid] - own;   // exclusive base
}

__global__ void scanC(int n_nodes) {
    int b = blockIdx.x;
    int lane = threadIdx.x;  // blockDim = 32
    int chunk = (n_nodes + NB_SCAN - 1) / NB_SCAN;
    int lo = b * chunk, hi = min(lo + chunk, n_nodes);
    if (lo >= n_nodes) return;
    int carry = g_partial[b];
    for (int i0 = lo; i0 < hi; i0 += 32) {
        int i = i0 + lane;
        int v = (i < hi) ? g_cnt[i] : 0;
        int incl = v;
        for (int off = 1; off < 32; off <<= 1) {
            int t = __shfl_up_sync(0xffffffffu, incl, off);
            if (lane >= off) incl += t;
        }
        int excl = incl - v;
        if (i < hi) {
            g_rowptr[i] = carry + excl;
            g_off[i] = carry + excl;
        }
        carry += __shfl_sync(0xffffffffu, incl, 31);
    }
    if (lane == 0 && hi == n_nodes) g_rowptr[n_nodes] = carry;
}

__global__ void fill_edges(const int* __restrict__ rows,
                           const int* __restrict__ cols, int n_edges) {
    const int is64 = g_idx64;
    for (int e = blockIdx.x * blockDim.x + threadIdx.x; e < n_edges;
         e += gridDim.x * blockDim.x) {
        int ei = is64 ? 2 * e : e;
        int r = rows[ei];
        int c = cols[ei];
        int pos = atomicAdd(&g_off[r], 1);
        g_edges[pos] = c;
    }
}

// ---------------------------------------------------------------------------
// sigmoid(x[s] @ W^T + b), s=0 -> out slice 0 (S), s=1 -> g_I (I)
// 64 nodes x 128 outputs per CTA, 256 threads, fma.rn.f32x2 packed pairs.
// ---------------------------------------------------------------------------
#define XPAD 66
__global__ __launch_bounds__(256, 3) void gemm_sigmoid(
    const float* __restrict__ x, const float* __restrict__ b,
    float* __restrict__ outS, float* __restrict__ outI, int n_nodes)
{
    __shared__ float XsT[H * XPAD];  // [k][node], even pad for LDS.64

    const int s = blockIdx.y;
    const int node0 = blockIdx.x * 64;
    const int tid = threadIdx.x;
    const float* xs = x + ((size_t)s * n_nodes + node0) * H;
    const int maxm = min(64, n_nodes - node0);

    const float4* xsrc = reinterpret_cast<const float4*>(xs);
    for (int i = tid; i < 64 * (H / 4); i += 256) {
        int m = i >> 5, q = i & 31;
        float4 v = make_float4(0.f, 0.f, 0.f, 0.f);
        if (m < maxm) v = xsrc[(size_t)m * (H / 4) + q];
        XsT[(4 * q + 0) * XPAD + m] = v.x;
        XsT[(4 * q + 1) * XPAD + m] = v.y;
        XsT[(4 * q + 2) * XPAD + m] = v.z;
        XsT[(4 * q + 3) * XPAD + m] = v.w;
    }
    __syncthreads();

    const int tx = tid & 31;
    const int ty = tid >> 5;

    const float4* Wt4 = reinterpret_cast<const float4*>(g_Wt);
    float4 bb = reinterpret_cast<const float4*>(b)[tx];

    unsigned long long acc[4][4];
    {
        unsigned long long b0, b1, b2, b3;
        asm("mov.b64 %0, {%1, %1};" : "=l"(b0) : "f"(bb.x));
        asm("mov.b64 %0, {%1, %1};" : "=l"(b1) : "f"(bb.y));
        asm("mov.b64 %0, {%1, %1};" : "=l"(b2) : "f"(bb.z));
        asm("mov.b64 %0, {%1, %1};" : "=l"(b3) : "f"(bb.w));
#pragma unroll
        for (int p = 0; p < 4; p++) {
            acc[p][0] = b0; acc[p][1] = b1; acc[p][2] = b2; acc[p][3] = b3;
        }
    }

    const int mbase = ty * 8;
#pragma unroll 2
    for (int k = 0; k < H; k++) {
        float4 w = __ldg(&Wt4[k * (H / 4) + tx]);
        unsigned long long wd[4];
        asm("mov.b64 %0, {%1, %1};" : "=l"(wd[0]) : "f"(w.x));
        asm("mov.b64 %0, {%1, %1};" : "=l"(wd[1]) : "f"(w.y));
        asm("mov.b64 %0, {%1, %1};" : "=l"(wd[2]) : "f"(w.z));
        asm("mov.b64 %0, {%1, %1};" : "=l"(wd[3]) : "f"(w.w));

        const float* xrow = &XsT[k * XPAD + mbase];
        unsigned long long xp[4];
#pragma unroll
        for (int p = 0; p < 4; p++)
            xp[p] = *reinterpret_cast<const unsigned long long*>(xrow + 2 * p);

#pragma unroll
        for (int p = 0; p < 4; p++) {
#pragma unroll
            for (int j = 0; j < 4; j++) {
                asm("fma.rn.f32x2 %0, %1, %2, %0;"
                    : "+l"(acc[p][j]) : "l"(xp[p]), "l"(wd[j]));
            }
        }
    }

    float* outp = (s == 0 ? outS : outI) + (size_t)node0 * H;
#pragma unroll
    for (int p = 0; p < 4; p++) {
        float lo[4], hi[4];
#pragma unroll
        for (int j = 0; j < 4; j++)
            asm("mov.b64 {%0, %1}, %2;" : "=f"(lo[j]), "=f"(hi[j]) : "l"(acc[p][j]));
        int m0 = mbase + 2 * p, m1 = m0 + 1;
        if (m0 < maxm) {
            float4 r;
            r.x = 1.f / (1.f + __expf(-lo[0]));
            r.y = 1.f / (1.f + __expf(-lo[1]));
            r.z = 1.f / (1.f + __expf(-lo[2]));
            r.w = 1.f / (1.f + __expf(-lo[3]));
            reinterpret_cast<float4*>(outp)[(size_t)m0 * (H / 4) + tx] = r;
        }
        if (m1 < maxm) {
            float4 r;
            r.x = 1.f / (1.f + __expf(-hi[0]));
            r.y = 1.f / (1.f + __expf(-hi[1]));
            r.z = 1.f / (1.f + __expf(-hi[2]));
            r.w = 1.f / (1.f + __expf(-hi[3]));
            reinterpret_cast<float4*>(outp)[(size_t)m1 * (H / 4) + tx] = r;
        }
    }
}

// ---------------------------------------------------------------------------
// Fused: AI (register segment-sum over CSR) + epilogue, one warp per row.
// Reads I rows from g_I (read-only), S from out slice 0 (same-warp rewrite).
// Writes all four output slices.
// ---------------------------------------------------------------------------
__global__ __launch_bounds__(256) void agg_finalize(
    const float* __restrict__ x, float* __restrict__ out, int n_nodes)
{
    const int lane = threadIdx.x & 31;
    const int r = (blockIdx.x * blockDim.x + threadIdx.x) >> 5;
    if (r >= n_nodes) return;

    int e = g_rowptr[r];
    const int end = g_rowptr[r + 1];
    const float4* I4 = reinterpret_cast<const float4*>(g_I);

    float4 ai = make_float4(0.f, 0.f, 0.f, 0.f);
    for (; e + 1 < end; e += 2) {
        int c0 = g_edges[e], c1 = g_edges[e + 1];
        float4 v0 = I4[(size_t)c0 * (H / 4) + lane];
        float4 v1 = I4[(size_t)c1 * (H / 4) + lane];
        ai.x += v0.x + v1.x; ai.y += v0.y + v1.y;
        ai.z += v0.z + v1.z; ai.w += v0.w + v1.w;
    }
    if (e < end) {
        int c = g_edges[e];
        float4 v = I4[(size_t)c * (H / 4) + lane];
        ai.x += v.x; ai.y += v.y; ai.z += v.z; ai.w += v.w;
    }

    float beta  = __ldg(&x[((size_t)3 * n_nodes + r) * H + 0]);
    float gamma = __ldg(&x[((size_t)3 * n_nodes + r) * H + 1]);

    float4* o4 = reinterpret_cast<float4*>(out);
    size_t sl = (size_t)n_nodes * (H / 4);
    size_t idx = (size_t)r * (H / 4) + lane;

    float4 S = o4[idx];
    float4 I = I4[idx];

    float4 dS, dI, dR;
    dS.x = -beta * ai.x * S.x;  dS.y = -beta * ai.y * S.y;
    dS.z = -beta * ai.z * S.z;  dS.w = -beta * ai.w * S.w;
    dI.x = -dS.x - gamma * I.x; dI.y = -dS.y - gamma * I.y;
    dI.z = -dS.z - gamma * I.z; dI.w = -dS.w - gamma * I.w;
    dR.x = gamma * I.x;  dR.y = gamma * I.y;
    dR.z = gamma * I.z;  dR.w = gamma * I.w;

    o4[idx] = dS;
    o4[sl + idx] = dI;
    o4[2 * sl + idx] = dR;
    o4[3 * sl + idx] = make_float4(0.f, 0.f, 0.f, 0.f);
}

// ---------------------------------------------------------------------------
extern "C" void kernel_launch(void* const* d_in, const int* in_sizes, int n_in,
                              void* d_out, int out_size)
{
    const float* x = (const float*)d_in[0];
    const float* W = (const float*)d_in[1];
    const float* b = (const float*)d_in[2];
    const int* rows = (const int*)d_in[3];
    const int* cols = (const int*)d_in[4];
    float* out = (float*)d_out;

    int n_nodes = in_sizes[0] / (4 * H);
    int n_edges = in_sizes[3];

    // Side stream + events created once on the first (eager) call, before
    // graph capture begins. Fork/join against the legacy stream is the
    // supported capture pattern.
    static cudaStream_t s2 = nullptr;
    static cudaEvent_t evFork = nullptr, evJoin = nullptr;
    if (s2 == nullptr) {
        cudaStreamCreateWithFlags(&s2, cudaStreamNonBlocking);
        cudaEventCreateWithFlags(&evFork, cudaEventDisableTiming);
        cudaEventCreateWithFlags(&evJoin, cudaEventDisableTiming);
    }

    float* g_I_ptr = nullptr;  // device address of g_I for pointer passing
    cudaGetSymbolAddress((void**)&g_I_ptr, g_I);

    // Fork: binning chain on s2, GEMM chain on the main (legacy) stream.
    cudaEventRecord(evFork, 0);
    cudaStreamWaitEvent(s2, evFork, 0);

    detect_idx_dtype<<<1, 1, 0, s2>>>(rows, n_edges);
    zero_cnt<<<(n_nodes + 255) / 256, 256, 0, s2>>>(n_nodes);
    count_rows<<<2048, 256, 0, s2>>>(rows, n_edges);
    scanA<<<NB_SCAN, 256, 0, s2>>>(n_nodes);
    scanB<<<1, NB_SCAN, 0, s2>>>();
    scanC<<<NB_SCAN, 32, 0, s2>>>(n_nodes);
    fill_edges<<<2048, 256, 0, s2>>>(rows, cols, n_edges);
    cudaEventRecord(evJoin, s2);

    // Main stream: W transpose + GEMM (independent of binning)
    transpose_W<<<(H * H + 255) / 256, 256>>>(W);
    dim3 g((n_nodes + 63) / 64, 2);
    gemm_sigmoid<<<g, 256>>>(x, b, out, g_I_ptr, n_nodes);

    // Join, then fused aggregation + epilogue
    cudaStreamWaitEvent(0, evJoin, 0);
    agg_finalize<<<(n_nodes * 32 + 255) / 256, 256>>>(x, out, n_nodes);
}

// round 6
// speedup vs baseline: 1.7446x; 1.2842x over previous
#include <cuda_runtime.h>
#include <cuda_fp16.h>

#define NODES_MAX 100000
#define EDGES_MAX 1600000
#define H 128
#define NB_SCAN 128
#define WS_STRIDE 132   // W smem row stride (floats): (4g+tig)%32 all-distinct
#define SMEM_W (H * WS_STRIDE * 4)

// Scratch (static device globals — no allocations allowed)
__device__ float g_I[(size_t)NODES_MAX * H];       // fp32 I (epilogue read)
__device__ __half2 g_Ih[(size_t)NODES_MAX * (H/2)]; // fp16 I (gather mirror)
__device__ int g_idx64;
__device__ int g_cnt[NODES_MAX];
__device__ int g_rowptr[NODES_MAX + 1];
__device__ int g_off[NODES_MAX];
__device__ int g_partial[NB_SCAN];
__device__ int g_edges[EDGES_MAX];

// ---------------------------------------------------------------------------
__global__ void detect_idx_dtype(const int* __restrict__ rows, int n_edges) {
    int or_odd = 0;
    int lim = min(n_edges, 128);
    for (int i = 1; i < lim; i += 2) or_odd |= rows[i];
    g_idx64 = (or_odd == 0) ? 1 : 0;
}

// ---------------------------------------------------------------------------
// CSR binning: zero -> count -> scan(3) -> fill
// ---------------------------------------------------------------------------
__global__ void zero_cnt(int n_nodes) {
    int i = blockIdx.x * blockDim.x + threadIdx.x;
    if (i < n_nodes) g_cnt[i] = 0;
}

__global__ void count_rows(const int* __restrict__ rows, int n_edges) {
    const int is64 = g_idx64;
    for (int e = blockIdx.x * blockDim.x + threadIdx.x; e < n_edges;
         e += gridDim.x * blockDim.x) {
        int r = rows[is64 ? 2 * e : e];
        atomicAdd(&g_cnt[r], 1);
    }
}

__global__ void scanA(int n_nodes) {
    __shared__ int sm[256];
    int chunk = (n_nodes + NB_SCAN - 1) / NB_SCAN;
    int b = blockIdx.x;
    int lo = b * chunk, hi = min(lo + chunk, n_nodes);
    int s = 0;
    for (int i = lo + threadIdx.x; i < hi; i += 256) s += g_cnt[i];
    sm[threadIdx.x] = s;
    __syncthreads();
    for (int off = 128; off > 0; off >>= 1) {
        if (threadIdx.x < off) sm[threadIdx.x] += sm[threadIdx.x + off];
        __syncthreads();
    }
    if (threadIdx.x == 0) g_partial[b] = sm[0];
}

__global__ void scanB() {
    __shared__ int sm[NB_SCAN];
    int tid = threadIdx.x;
    int own = g_partial[tid];
    sm[tid] = own;
    __syncthreads();
    for (int off = 1; off < NB_SCAN; off <<= 1) {
        int v = (tid >= off) ? sm[tid - off] : 0;
        __syncthreads();
        sm[tid] += v;
        __syncthreads();
    }
    g_partial[tid] = sm[tid] - own;
}

__global__ void scanC(int n_nodes) {
    int b = blockIdx.x;
    int lane = threadIdx.x;  // blockDim = 32
    int chunk = (n_nodes + NB_SCAN - 1) / NB_SCAN;
    int lo = b * chunk, hi = min(lo + chunk, n_nodes);
    if (lo >= n_nodes) return;
    int carry = g_partial[b];
    for (int i0 = lo; i0 < hi; i0 += 32) {
        int i = i0 + lane;
        int v = (i < hi) ? g_cnt[i] : 0;
        int incl = v;
        for (int off = 1; off < 32; off <<= 1) {
            int t = __shfl_up_sync(0xffffffffu, incl, off);
            if (lane >= off) incl += t;
        }
        int excl = incl - v;
        if (i < hi) {
            g_rowptr[i] = carry + excl;
            g_off[i] = carry + excl;
        }
        carry += __shfl_sync(0xffffffffu, incl, 31);
    }
    if (lane == 0 && hi == n_nodes) g_rowptr[n_nodes] = carry;
}

__global__ void fill_edges(const int* __restrict__ rows,
                           const int* __restrict__ cols, int n_edges) {
    const int is64 = g_idx64;
    for (int e = blockIdx.x * blockDim.x + threadIdx.x; e < n_edges;
         e += gridDim.x * blockDim.x) {
        int ei = is64 ? 2 * e : e;
        int r = rows[ei];
        int c = cols[ei];
        int pos = atomicAdd(&g_off[r], 1);
        g_edges[pos] = c;
    }
}

// ---------------------------------------------------------------------------
// TF32 tensor-core GEMM + sigmoid.
// CTA: 256 thr (8 warps), 128 nodes; warp = 16 nodes x 128 outputs.
// mma.sync.m16n8k8.row.col tf32; W tf32-converted in smem (stride 132,
// conflict-free B-frag LDS); A frags straight from global with prefetch.
// s=0 -> outS (fp32). s=1 -> g_I (fp32) + g_Ih (half2 gather mirror).
// ---------------------------------------------------------------------------
__device__ __forceinline__ unsigned f2tf32(float f) {
    unsigned u;
    asm("cvt.rna.tf32.f32 %0, %1;" : "=r"(u) : "f"(f));
    return u;
}

__global__ __launch_bounds__(256, 2) void gemm_sigmoid_tf32(
    const float* __restrict__ x, const float* __restrict__ W,
    const float* __restrict__ b, float* __restrict__ outS,
    float* __restrict__ outI, __half2* __restrict__ outIh, int n_nodes)
{
    extern __shared__ float Ws[];   // [128][WS_STRIDE], tf32-converted

    const int s = blockIdx.y;
    const int tid = threadIdx.x;

    // Stage W into smem (convert to tf32 once)
    for (int i = tid; i < H * H; i += 256) {
        int o = i >> 7, k = i & 127;
        Ws[o * WS_STRIDE + k] = __uint_as_float(f2tf32(W[i]));
    }
    __syncthreads();

    const int warp = tid >> 5, lane = tid & 31;
    const int g = lane >> 2, tig = lane & 3;
    const int m0 = blockIdx.x * 128 + warp * 16;
    if (m0 >= n_nodes) return;

    const int r0 = min(m0 + g, n_nodes - 1);
    const int r1 = min(m0 + g + 8, n_nodes - 1);
    const float* xs = x + (size_t)s * n_nodes * H;
    const float* xr0 = xs + (size_t)r0 * H;
    const float* xr1 = xs + (size_t)r1 * H;

    // Accumulators initialized with bias (c0/c2 -> col 2tig, c1/c3 -> 2tig+1)
    float c[16][4];
#pragma unroll
    for (int nt = 0; nt < 16; nt++) {
        float b0 = __ldg(&b[nt * 8 + 2 * tig]);
        float b1 = __ldg(&b[nt * 8 + 2 * tig + 1]);
        c[nt][0] = b0; c[nt][1] = b1; c[nt][2] = b0; c[nt][3] = b1;
    }

    // A fragment prefetch pipeline (floats; convert at use)
    float f0 = xr0[tig],     f1 = xr1[tig];
    float f2 = xr0[tig + 4], f3 = xr1[tig + 4];

    for (int kt = 0; kt < 16; kt++) {
        unsigned a0 = f2tf32(f0), a1 = f2tf32(f1);
        unsigned a2 = f2tf32(f2), a3 = f2tf32(f3);
        if (kt < 15) {
            int kb = (kt + 1) * 8;
            f0 = xr0[kb + tig];     f1 = xr1[kb + tig];
            f2 = xr0[kb + tig + 4]; f3 = xr1[kb + tig + 4];
        }
        const float* wb = Ws + kt * 8 + tig;
#pragma unroll
        for (int nt = 0; nt < 16; nt++) {
            unsigned b0 = __float_as_uint(wb[(nt * 8 + g) * WS_STRIDE]);
            unsigned b1 = __float_as_uint(wb[(nt * 8 + g) * WS_STRIDE + 4]);
            asm("mma.sync.aligned.m16n8k8.row.col.f32.tf32.tf32.f32 "
                "{%0,%1,%2,%3}, {%4,%5,%6,%7}, {%8,%9}, {%0,%1,%2,%3};"
                : "+f"(c[nt][0]), "+f"(c[nt][1]), "+f"(c[nt][2]), "+f"(c[nt][3])
                : "r"(a0), "r"(a1), "r"(a2), "r"(a3), "r"(b0), "r"(b1));
        }
    }

    const int mA = m0 + g, mB = m0 + g + 8;
    const bool okA = mA < n_nodes, okB = mB < n_nodes;
#pragma unroll
    for (int nt = 0; nt < 16; nt++) {
        int o = nt * 8 + 2 * tig;
        float2 lo, hi;
        lo.x = 1.f / (1.f + __expf(-c[nt][0]));
        lo.y = 1.f / (1.f + __expf(-c[nt][1]));
        hi.x = 1.f / (1.f + __expf(-c[nt][2]));
        hi.y = 1.f / (1.f + __expf(-c[nt][3]));
        if (s == 0) {
            if (okA) *reinterpret_cast<float2*>(&outS[(size_t)mA * H + o]) = lo;
            if (okB) *reinterpret_cast<float2*>(&outS[(size_t)mB * H + o]) = hi;
        } else {
            if (okA) {
                *reinterpret_cast<float2*>(&outI[(size_t)mA * H + o]) = lo;
                outIh[(size_t)mA * (H / 2) + (o >> 1)] = __floats2half2_rn(lo.x, lo.y);
            }
            if (okB) {
                *reinterpret_cast<float2*>(&outI[(size_t)mB * H + o]) = hi;
                outIh[(size_t)mB * (H / 2) + (o >> 1)] = __floats2half2_rn(hi.x, hi.y);
            }
        }
    }
}

// ---------------------------------------------------------------------------
// Fused: AI segment-sum (fp16 gather from g_Ih, fp32 accumulate) + epilogue.
// One warp per row; lane covers cols [4*lane, 4*lane+4).
// ---------------------------------------------------------------------------
__global__ __launch_bounds__(256) void agg_finalize(
    const float* __restrict__ x, float* __restrict__ out, int n_nodes)
{
    const int lane = threadIdx.x & 31;
    const int r = (blockIdx.x * blockDim.x + threadIdx.x) >> 5;
    if (r >= n_nodes) return;

    int e = g_rowptr[r];
    const int end = g_rowptr[r + 1];
    const uint2* Ih = reinterpret_cast<const uint2*>(g_Ih);  // 8B = 4 halves

    float4 ai = make_float4(0.f, 0.f, 0.f, 0.f);
    for (; e + 1 < end; e += 2) {
        int c0 = g_edges[e], c1 = g_edges[e + 1];
        uint2 v0 = Ih[(size_t)c0 * 32 + lane];
        uint2 v1 = Ih[(size_t)c1 * 32 + lane];
        float2 p0 = __half22float2(*reinterpret_cast<__half2*>(&v0.x));
        float2 p1 = __half22float2(*reinterpret_cast<__half2*>(&v0.y));
        float2 q0 = __half22float2(*reinterpret_cast<__half2*>(&v1.x));
        float2 q1 = __half22float2(*reinterpret_cast<__half2*>(&v1.y));
        ai.x += p0.x + q0.x; ai.y += p0.y + q0.y;
        ai.z += p1.x + q1.x; ai.w += p1.y + q1.y;
    }
    if (e < end) {
        int c = g_edges[e];
        uint2 v = Ih[(size_t)c * 32 + lane];
        float2 p0 = __half22float2(*reinterpret_cast<__half2*>(&v.x));
        float2 p1 = __half22float2(*reinterpret_cast<__half2*>(&v.y));
        ai.x += p0.x; ai.y += p0.y; ai.z += p1.x; ai.w += p1.y;
    }

    float beta  = __ldg(&x[((size_t)3 * n_nodes + r) * H + 0]);
    float gamma = __ldg(&x[((size_t)3 * n_nodes + r) * H + 1]);

    float4* o4 = reinterpret_cast<float4*>(out);
    size_t sl = (size_t)n_nodes * (H / 4);
    size_t idx = (size_t)r * (H / 4) + lane;

    float4 S = o4[idx];
    float4 I = reinterpret_cast<const float4*>(g_I)[idx];

    float4 dS, dI, dR;
    dS.x = -beta * ai.x * S.x;  dS.y = -beta * ai.y * S.y;
    dS.z = -beta * ai.z * S.z;  dS.w = -beta * ai.w * S.w;
    dI.x = -dS.x - gamma * I.x; dI.y = -dS.y - gamma * I.y;
    dI.z = -dS.z - gamma * I.z; dI.w = -dS.w - gamma * I.w;
    dR.x = gamma * I.x;  dR.y = gamma * I.y;
    dR.z = gamma * I.z;  dR.w = gamma * I.w;

    o4[idx] = dS;
    o4[sl + idx] = dI;
    o4[2 * sl + idx] = dR;
    o4[3 * sl + idx] = make_float4(0.f, 0.f, 0.f, 0.f);
}

// ---------------------------------------------------------------------------
extern "C" void kernel_launch(void* const* d_in, const int* in_sizes, int n_in,
                              void* d_out, int out_size)
{
    const float* x = (const float*)d_in[0];
    const float* W = (const float*)d_in[1];
    const float* b = (const float*)d_in[2];
    const int* rows = (const int*)d_in[3];
    const int* cols = (const int*)d_in[4];
    float* out = (float*)d_out;

    int n_nodes = in_sizes[0] / (4 * H);
    int n_edges = in_sizes[3];

    static cudaStream_t s2 = nullptr;
    static cudaEvent_t evFork = nullptr, evJoin = nullptr;
    if (s2 == nullptr) {
        cudaStreamCreateWithFlags(&s2, cudaStreamNonBlocking);
        cudaEventCreateWithFlags(&evFork, cudaEventDisableTiming);
        cudaEventCreateWithFlags(&evJoin, cudaEventDisableTiming);
        cudaFuncSetAttribute(gemm_sigmoid_tf32,
                             cudaFuncAttributeMaxDynamicSharedMemorySize, SMEM_W);
    }

    float* g_I_ptr = nullptr;
    __half2* g_Ih_ptr = nullptr;
    cudaGetSymbolAddress((void**)&g_I_ptr, g_I);
    cudaGetSymbolAddress((void**)&g_Ih_ptr, g_Ih);

    // Fork: binning on s2; GEMM on main stream.
    cudaEventRecord(evFork, 0);
    cudaStreamWaitEvent(s2, evFork, 0);

    detect_idx_dtype<<<1, 1, 0, s2>>>(rows, n_edges);
    zero_cnt<<<(n_nodes + 255) / 256, 256, 0, s2>>>(n_nodes);
    count_rows<<<2048, 256, 0, s2>>>(rows, n_edges);
    scanA<<<NB_SCAN, 256, 0, s2>>>(n_nodes);
    scanB<<<1, NB_SCAN, 0, s2>>>();
    scanC<<<NB_SCAN, 32, 0, s2>>>(n_nodes);
    fill_edges<<<2048, 256, 0, s2>>>(rows, cols, n_edges);
    cudaEventRecord(evJoin, s2);

    dim3 g((n_nodes + 127) / 128, 2);
    gemm_sigmoid_tf32<<<g, 256, SMEM_W>>>(x, W, b, out, g_I_ptr, g_Ih_ptr,
                                          n_nodes);

    cudaStreamWaitEvent(0, evJoin, 0);
    agg_finalize<<<(n_nodes * 32 + 255) / 256, 256>>>(x, out, n_nodes);
}